// round 3
// baseline (speedup 1.0000x reference)
#include <cuda_runtime.h>
#include <cuda_bf16.h>
#include <math.h>
#include <stdint.h>

#define B_    8192
#define D_    1024
#define H_    4096
#define O_    1024
#define E_    8
#define KSEL  2
#define NPAIR (B_*KSEL)
#define AVG_CH 16

// ---------------- device scratch (static, no allocation) ----------------
__device__ __nv_bfloat16 g_x_hi[(size_t)B_*D_];
__device__ __nv_bfloat16 g_x_lo[(size_t)B_*D_];
__device__ __nv_bfloat16 g_w1_hi[(size_t)E_*D_*H_];
__device__ __nv_bfloat16 g_w1_lo[(size_t)E_*D_*H_];
__device__ __nv_bfloat16 g_w2_hi[(size_t)E_*H_*O_];
__device__ __nv_bfloat16 g_w2_lo[(size_t)E_*H_*O_];
__device__ __nv_bfloat16 g_h_hi[(size_t)NPAIR*H_];
__device__ __nv_bfloat16 g_h_lo[(size_t)NPAIR*H_];
__device__ float g_out_buf[(size_t)NPAIR*O_];
__device__ float g_gates[(size_t)B_*E_];
__device__ int   g_top_idx[B_*KSEL];
__device__ float g_top_w[B_*KSEL];
__device__ int   g_counts[E_];
__device__ int   g_cursor[E_];
__device__ int   g_offset[E_];
__device__ int   g_list[NPAIR];
__device__ int   g_slot[B_*KSEL];
__device__ float g_usage[E_];
__device__ float g_avg_part[E_*AVG_CH*O_];
__device__ float g_avgs[E_*O_];

// ---------------- small helpers ----------------
__device__ __forceinline__ void cp16(void* s, const void* g) {
    unsigned sa = (unsigned)__cvta_generic_to_shared(s);
    asm volatile("cp.async.ca.shared.global [%0], [%1], 16;\n" :: "r"(sa), "l"(g));
}
__device__ __forceinline__ void cp_commit() { asm volatile("cp.async.commit_group;\n"); }

__device__ __forceinline__ void ldm4(unsigned* r, const void* p) {
    unsigned a = (unsigned)__cvta_generic_to_shared(p);
    asm volatile("ldmatrix.sync.aligned.m8n8.x4.shared.b16 {%0,%1,%2,%3}, [%4];\n"
        : "=r"(r[0]), "=r"(r[1]), "=r"(r[2]), "=r"(r[3]) : "r"(a));
}
__device__ __forceinline__ void ldm2t(unsigned* r, const void* p) {
    unsigned a = (unsigned)__cvta_generic_to_shared(p);
    asm volatile("ldmatrix.sync.aligned.m8n8.x2.trans.shared.b16 {%0,%1}, [%2];\n"
        : "=r"(r[0]), "=r"(r[1]) : "r"(a));
}
__device__ __forceinline__ void mma16816(float* d, const unsigned* a, const unsigned* b) {
    asm volatile("mma.sync.aligned.m16n8k16.row.col.f32.bf16.bf16.f32 "
        "{%0,%1,%2,%3}, {%4,%5,%6,%7}, {%8,%9}, {%0,%1,%2,%3};\n"
        : "+f"(d[0]), "+f"(d[1]), "+f"(d[2]), "+f"(d[3])
        : "r"(a[0]), "r"(a[1]), "r"(a[2]), "r"(a[3]), "r"(b[0]), "r"(b[1]));
}

// ---------------- prep: fp32 -> bf16 hi/lo split ----------------
__global__ void moe_split(const float* __restrict__ src,
                          __nv_bfloat16* __restrict__ hi,
                          __nv_bfloat16* __restrict__ lo, int n4) {
    int i = blockIdx.x * blockDim.x + threadIdx.x;
    if (i >= n4) return;
    float4 v = ((const float4*)src)[i];
    __nv_bfloat16 h0 = __float2bfloat16(v.x);
    __nv_bfloat16 h1 = __float2bfloat16(v.y);
    __nv_bfloat16 h2 = __float2bfloat16(v.z);
    __nv_bfloat16 h3 = __float2bfloat16(v.w);
    __nv_bfloat162 a, b;
    a.x = h0; a.y = h1; b.x = h2; b.y = h3;
    ((__nv_bfloat162*)hi)[i*2]   = a;
    ((__nv_bfloat162*)hi)[i*2+1] = b;
    __nv_bfloat162 c, d;
    c.x = __float2bfloat16(v.x - __bfloat162float(h0));
    c.y = __float2bfloat16(v.y - __bfloat162float(h1));
    d.x = __float2bfloat16(v.z - __bfloat162float(h2));
    d.y = __float2bfloat16(v.w - __bfloat162float(h3));
    ((__nv_bfloat162*)lo)[i*2]   = c;
    ((__nv_bfloat162*)lo)[i*2+1] = d;
}

// ---------------- init / gate / routing ----------------
__global__ void moe_init() {
    int t = threadIdx.x;
    if (t < E_) { g_counts[t] = 0; g_cursor[t] = 0; }
}

__global__ void moe_gate(const float* __restrict__ x, const float* __restrict__ gw,
                         const float* __restrict__ gb) {
    int b = blockIdx.x;
    int tid = threadIdx.x;
    const float* xr = x + (size_t)b * D_;
    float acc[E_];
    #pragma unroll
    for (int e = 0; e < E_; e++) acc[e] = 0.f;
    for (int d = tid; d < D_; d += 128) {
        float xv = xr[d];
        const float* g = gw + d * E_;
        #pragma unroll
        for (int e = 0; e < E_; e++) acc[e] += xv * g[e];
    }
    __shared__ float s[E_][128];
    #pragma unroll
    for (int e = 0; e < E_; e++) s[e][tid] = acc[e];
    __syncthreads();
    if (tid < E_) {
        float t = 0.f;
        for (int i = 0; i < 128; i++) t += s[tid][i];
        s[tid][0] = t + gb[tid];
    }
    __syncthreads();
    if (tid == 0) {
        float logit[E_], ex[E_];
        float mx = -1e30f;
        #pragma unroll
        for (int e = 0; e < E_; e++) { logit[e] = s[e][0]; mx = fmaxf(mx, logit[e]); }
        float sum = 0.f;
        #pragma unroll
        for (int e = 0; e < E_; e++) { ex[e] = expf(logit[e] - mx); sum += ex[e]; }
        float inv = 1.f / sum;
        float gts[E_];
        #pragma unroll
        for (int e = 0; e < E_; e++) { gts[e] = ex[e] * inv; g_gates[(size_t)b*E_ + e] = gts[e]; }
        int i0 = 0;
        #pragma unroll
        for (int e = 1; e < E_; e++) if (gts[e] > gts[i0]) i0 = e;
        int i1 = (i0 == 0) ? 1 : 0;
        #pragma unroll
        for (int e = 0; e < E_; e++) if (e != i0 && gts[e] > gts[i1]) i1 = e;
        float v0 = gts[i0], v1 = gts[i1];
        float ws = 1.f / (v0 + v1);
        g_top_idx[b*2]   = i0; g_top_w[b*2]   = v0 * ws;
        g_top_idx[b*2+1] = i1; g_top_w[b*2+1] = v1 * ws;
        atomicAdd(&g_counts[i0], 1);
        atomicAdd(&g_counts[i1], 1);
    }
}

__global__ void moe_usage() {
    int e = blockIdx.x, tid = threadIdx.x;
    float a = 0.f;
    for (int b = tid; b < B_; b += 256) a += g_gates[(size_t)b*E_ + e];
    __shared__ float s[256];
    s[tid] = a; __syncthreads();
    for (int st = 128; st > 0; st >>= 1) {
        if (tid < st) s[tid] += s[tid + st];
        __syncthreads();
    }
    if (tid == 0) g_usage[e] = s[0] / (float)B_;
}

__global__ void moe_offsets() {
    if (threadIdx.x == 0) {
        int acc = 0;
        for (int e = 0; e < E_; e++) { g_offset[e] = acc; acc += g_counts[e]; }
    }
}

__global__ void moe_scatter() {
    int b = blockIdx.x * blockDim.x + threadIdx.x;
    if (b >= B_) return;
    #pragma unroll
    for (int j = 0; j < KSEL; j++) {
        int e = g_top_idx[b*2 + j];
        int p = g_offset[e] + atomicAdd(&g_cursor[e], 1);
        g_list[p] = b;
        g_slot[b*2 + j] = p;
    }
}

// ---------------- grouped GEMM (bf16x3 split, mma.sync) ----------------
// PHASE1: A = gathered x rows (K=D), B = W1[e], epilogue bias+ReLU -> h hi/lo
// PHASE2: A = h rows (contiguous), B = W2[e], epilogue bias -> out_buf fp32
#define A_STR 40
#define B_STR 136
#define A_ELE (128*A_STR)
#define B_ELE (32*B_STR)
#define SMEM_BYTES ((4*A_ELE + 4*B_ELE) * 2)

template<bool PHASE1>
__global__ __launch_bounds__(256, 1) void moe_gemm(const float* __restrict__ bias_all) {
    constexpr int Kdim = PHASE1 ? D_ : H_;
    constexpr int N    = PHASE1 ? H_ : O_;
    constexpr int NKT  = Kdim / 32;

    int e = blockIdx.z;
    int cnt = g_counts[e];
    int mbase = blockIdx.y * 128;
    if (mbase >= cnt) return;
    int off = g_offset[e];
    int nbase = blockIdx.x * 128;

    const __nv_bfloat16* __restrict__ Bh;
    const __nv_bfloat16* __restrict__ Bl;
    if (PHASE1) {
        Bh = g_w1_hi + (size_t)e * D_ * H_;
        Bl = g_w1_lo + (size_t)e * D_ * H_;
    } else {
        Bh = g_w2_hi + (size_t)e * H_ * O_;
        Bl = g_w2_lo + (size_t)e * H_ * O_;
    }
    const float* __restrict__ bias_e = bias_all + (size_t)e * N;

    extern __shared__ char smem_raw[];
    __nv_bfloat16* sA = (__nv_bfloat16*)smem_raw;                       // [2][2][A_ELE]
    __nv_bfloat16* sB = (__nv_bfloat16*)(smem_raw + 4 * A_ELE * 2);     // [2][2][B_ELE]

    int tid = threadIdx.x;
    int lane = tid & 31, warp = tid >> 5;
    int wm = warp & 1, wn = warp >> 1;

    auto load_stage = [&](int kt, int stage) {
        int k0 = kt * 32;
        __nv_bfloat16* ah = sA + (stage*2 + 0) * A_ELE;
        __nv_bfloat16* al = sA + (stage*2 + 1) * A_ELE;
        #pragma unroll
        for (int it = 0; it < 2; it++) {
            int c = tid + it * 256;
            int row = c >> 2, seg = c & 3;
            size_t base;
            if (PHASE1) {
                int rg = mbase + row;
                int t = (rg < cnt) ? g_list[off + rg] : g_list[off];
                base = (size_t)t * D_ + k0 + seg * 8;
                cp16(ah + row*A_STR + seg*8, g_x_hi + base);
                cp16(al + row*A_STR + seg*8, g_x_lo + base);
            } else {
                size_t r = (size_t)off + mbase + row;
                if (r >= NPAIR) r = 0;
                base = r * (size_t)H_ + k0 + seg * 8;
                cp16(ah + row*A_STR + seg*8, g_h_hi + base);
                cp16(al + row*A_STR + seg*8, g_h_lo + base);
            }
        }
        __nv_bfloat16* bh = sB + (stage*2 + 0) * B_ELE;
        __nv_bfloat16* bl = sB + (stage*2 + 1) * B_ELE;
        #pragma unroll
        for (int it = 0; it < 2; it++) {
            int c = tid + it * 256;
            int row = c >> 4, seg = c & 15;
            size_t base = (size_t)(k0 + row) * N + nbase + seg * 8;
            cp16(bh + row*B_STR + seg*8, Bh + base);
            cp16(bl + row*B_STR + seg*8, Bl + base);
        }
    };

    float acc[4][4][4];
    #pragma unroll
    for (int i = 0; i < 4; i++)
        #pragma unroll
        for (int j = 0; j < 4; j++)
            #pragma unroll
            for (int k = 0; k < 4; k++) acc[i][j][k] = 0.f;

    load_stage(0, 0);
    cp_commit();

    for (int kt = 0; kt < NKT; kt++) {
        if (kt + 1 < NKT) {
            load_stage(kt + 1, (kt + 1) & 1);
            cp_commit();
            asm volatile("cp.async.wait_group 1;\n");
        } else {
            asm volatile("cp.async.wait_group 0;\n");
        }
        __syncthreads();

        int stage = kt & 1;
        const __nv_bfloat16* Ahs = sA + (stage*2 + 0) * A_ELE;
        const __nv_bfloat16* Als = sA + (stage*2 + 1) * A_ELE;
        const __nv_bfloat16* Bhs = sB + (stage*2 + 0) * B_ELE;
        const __nv_bfloat16* Bls = sB + (stage*2 + 1) * B_ELE;

        #pragma unroll
        for (int ks = 0; ks < 32; ks += 16) {
            unsigned ah[4][4], al[4][4];
            int ar = wm*64 + (lane & 15);
            int acw = ks + ((lane >> 4) << 3);
            #pragma unroll
            for (int mi = 0; mi < 4; mi++) {
                ldm4(ah[mi], Ahs + (ar + mi*16) * A_STR + acw);
                ldm4(al[mi], Als + (ar + mi*16) * A_STR + acw);
            }
            unsigned bh[4][2], bl[4][2];
            int kk = ks + (lane & 15);
            #pragma unroll
            for (int nj = 0; nj < 4; nj++) {
                int cc = wn*32 + nj*8;
                ldm2t(bh[nj], Bhs + kk * B_STR + cc);
                ldm2t(bl[nj], Bls + kk * B_STR + cc);
            }
            #pragma unroll
            for (int mi = 0; mi < 4; mi++)
                #pragma unroll
                for (int nj = 0; nj < 4; nj++) {
                    mma16816(acc[mi][nj], ah[mi], bh[nj]);
                    mma16816(acc[mi][nj], ah[mi], bl[nj]);
                    mma16816(acc[mi][nj], al[mi], bh[nj]);
                }
        }
        __syncthreads();
    }

    // epilogue
    #pragma unroll
    for (int mi = 0; mi < 4; mi++) {
        #pragma unroll
        for (int nj = 0; nj < 4; nj++) {
            int rloc = wm*64 + mi*16 + (lane >> 2);
            int col0 = nbase + wn*32 + nj*8 + (lane & 3) * 2;
            float bv0 = bias_e[col0], bv1 = bias_e[col0 + 1];
            #pragma unroll
            for (int half = 0; half < 2; half++) {
                int rg = mbase + rloc + half * 8;
                if (rg < cnt) {
                    float v0 = acc[mi][nj][half*2]     + bv0;
                    float v1 = acc[mi][nj][half*2 + 1] + bv1;
                    size_t rp = (size_t)(off + rg);
                    if (PHASE1) {
                        v0 = fmaxf(v0, 0.f); v1 = fmaxf(v1, 0.f);
                        __nv_bfloat16 h0 = __float2bfloat16(v0);
                        __nv_bfloat16 h1 = __float2bfloat16(v1);
                        __nv_bfloat162 hh; hh.x = h0; hh.y = h1;
                        *(__nv_bfloat162*)(g_h_hi + rp * H_ + col0) = hh;
                        __nv_bfloat162 ll;
                        ll.x = __float2bfloat16(v0 - __bfloat162float(h0));
                        ll.y = __float2bfloat16(v1 - __bfloat162float(h1));
                        *(__nv_bfloat162*)(g_h_lo + rp * H_ + col0) = ll;
                    } else {
                        float2 f; f.x = v0; f.y = v1;
                        *(float2*)(g_out_buf + rp * O_ + col0) = f;
                    }
                }
            }
        }
    }
}

// ---------------- epilogues ----------------
__global__ void moe_combine(float* __restrict__ out) {
    int b = blockIdx.x, t = threadIdx.x;
    int s0 = g_slot[b*2], s1 = g_slot[b*2 + 1];
    float w0 = g_top_w[b*2], w1 = g_top_w[b*2 + 1];
    float4 a = ((const float4*)(g_out_buf + (size_t)s0 * O_))[t];
    float4 c = ((const float4*)(g_out_buf + (size_t)s1 * O_))[t];
    float4 r;
    r.x = w0*a.x + w1*c.x; r.y = w0*a.y + w1*c.y;
    r.z = w0*a.z + w1*c.z; r.w = w0*a.w + w1*c.w;
    ((float4*)(out + (size_t)b * O_))[t] = r;
}

__global__ void moe_avg_part() {
    int e = blockIdx.x, cb = blockIdx.y, ch = blockIdx.z;
    int col = cb * 128 + threadIdx.x;
    int cnt = g_counts[e], off = g_offset[e];
    int per = (cnt + AVG_CH - 1) / AVG_CH;
    int r0 = ch * per;
    int r1 = min(r0 + per, cnt);
    float a = 0.f;
    for (int r = r0; r < r1; r++) a += g_out_buf[(size_t)(off + r) * O_ + col];
    g_avg_part[((size_t)(e * AVG_CH) + ch) * O_ + col] = a;
}

__global__ void moe_avg_fin() {
    int e = blockIdx.x;
    int col = blockIdx.y * 128 + threadIdx.x;
    float a = 0.f;
    #pragma unroll
    for (int c = 0; c < AVG_CH; c++) a += g_avg_part[((size_t)(e * AVG_CH) + c) * O_ + col];
    int cnt = g_counts[e];
    g_avgs[(size_t)e * O_ + col] = a / fmaxf((float)cnt, 1.0f);
}

__global__ void moe_loss(float* __restrict__ out) {
    int tid = threadIdx.x;
    __shared__ float red[256];
    __shared__ float total;
    if (tid == 0) total = 0.f;
    __syncthreads();
    for (int i = 0; i < E_; i++) {
        for (int j = i + 1; j < E_; j++) {
            float s = 0.f;
            bool ok = (g_counts[i] > 0) && (g_counts[j] > 0);
            if (ok) {
                for (int c = tid; c < O_; c += 256) {
                    float d = g_avgs[(size_t)i*O_ + c] - g_avgs[(size_t)j*O_ + c];
                    s += d * d;
                }
            }
            red[tid] = s; __syncthreads();
            for (int st = 128; st > 0; st >>= 1) {
                if (tid < st) red[tid] += red[tid + st];
                __syncthreads();
            }
            if (tid == 0 && ok) total += expf(-red[0] * 0.5f);
            __syncthreads();
        }
    }
    if (tid == 0) {
        out[(size_t)B_ * O_] = total;
        float s = 0.f;
        #pragma unroll
        for (int e = 0; e < E_; e++) {
            float d = g_usage[e] - 1.0f / (float)E_;
            s += d * d;
        }
        out[(size_t)B_ * O_ + 1] = sqrtf(s);
    }
}

// ---------------- launcher ----------------
extern "C" void kernel_launch(void* const* d_in, const int* in_sizes, int n_in,
                              void* d_out, int out_size) {
    const float* x   = (const float*)d_in[0];
    const float* gW  = (const float*)d_in[1];
    const float* gb  = (const float*)d_in[2];
    const float* W1  = (const float*)d_in[3];
    const float* b1  = (const float*)d_in[4];
    const float* W2  = (const float*)d_in[5];
    const float* b2  = (const float*)d_in[6];
    float* out = (float*)d_out;

    cudaFuncSetAttribute(moe_gemm<true>,  cudaFuncAttributeMaxDynamicSharedMemorySize, SMEM_BYTES);
    cudaFuncSetAttribute(moe_gemm<false>, cudaFuncAttributeMaxDynamicSharedMemorySize, SMEM_BYTES);

    // resolve __device__ symbol addresses for split targets
    __nv_bfloat16 *xh, *xl, *w1h, *w1l, *w2h, *w2l;
    cudaGetSymbolAddress((void**)&xh,  g_x_hi);
    cudaGetSymbolAddress((void**)&xl,  g_x_lo);
    cudaGetSymbolAddress((void**)&w1h, g_w1_hi);
    cudaGetSymbolAddress((void**)&w1l, g_w1_lo);
    cudaGetSymbolAddress((void**)&w2h, g_w2_hi);
    cudaGetSymbolAddress((void**)&w2l, g_w2_lo);

    moe_init<<<1, 32>>>();

    {
        int n4 = (B_ * D_) / 4;
        moe_split<<<(n4 + 255) / 256, 256>>>(x, xh, xl, n4);
    }
    {
        int n4 = (E_ * D_ * H_) / 4;
        moe_split<<<(n4 + 255) / 256, 256>>>(W1, w1h, w1l, n4);
    }
    {
        int n4 = (E_ * H_ * O_) / 4;
        moe_split<<<(n4 + 255) / 256, 256>>>(W2, w2h, w2l, n4);
    }

    moe_gate<<<B_, 128>>>(x, gW, gb);
    moe_usage<<<E_, 256>>>();
    moe_offsets<<<1, 1>>>();
    moe_scatter<<<(B_ + 255) / 256, 256>>>();

    moe_gemm<true><<<dim3(H_ / 128, 128, E_), 256, SMEM_BYTES>>>(b1);
    moe_gemm<false><<<dim3(O_ / 128, 128, E_), 256, SMEM_BYTES>>>(b2);

    moe_combine<<<B_, 256>>>(out);
    moe_avg_part<<<dim3(E_, O_ / 128, AVG_CH), 128>>>();
    moe_avg_fin<<<dim3(E_, O_ / 128), 128>>>();
    moe_loss<<<1, 256>>>(out);

    (void)in_sizes; (void)n_in; (void)out_size;
}

// round 5
// speedup vs baseline: 2.0051x; 2.0051x over previous
#include <cuda_runtime.h>
#include <cuda_bf16.h>
#include <cuda_fp16.h>
#include <math.h>
#include <stdint.h>

#define B_    8192
#define D_    1024
#define H_    4096
#define O_    1024
#define E_    8
#define KSEL  2
#define NPAIR (B_*KSEL)
#define AVG_CH 16

// ---------------- device scratch (static, no allocation) ----------------
__device__ __half g_x_f16[(size_t)B_*D_];
__device__ __half g_w1_f16[(size_t)E_*D_*H_];   // (E, D, H) K-major rows
__device__ __half g_w2_f16[(size_t)E_*H_*O_];   // (E, H, O)
__device__ __half g_h_f16[(size_t)NPAIR*H_];
__device__ float g_out_buf[(size_t)NPAIR*O_];
__device__ float g_gates[(size_t)B_*E_];
__device__ int   g_top_idx[B_*KSEL];
__device__ float g_top_w[B_*KSEL];
__device__ int   g_counts[E_];
__device__ int   g_cursor[E_];
__device__ int   g_offset[E_];
__device__ int   g_list[NPAIR];
__device__ int   g_slot[B_*KSEL];
__device__ float g_usage[E_];
__device__ float g_avg_part[E_*AVG_CH*O_];
__device__ float g_avgs[E_*O_];

// ---------------- PTX helpers ----------------
__device__ __forceinline__ void cp16(void* s, const void* g) {
    unsigned sa = (unsigned)__cvta_generic_to_shared(s);
    asm volatile("cp.async.ca.shared.global [%0], [%1], 16;\n" :: "r"(sa), "l"(g));
}
__device__ __forceinline__ void cp_commit() { asm volatile("cp.async.commit_group;\n"); }
#define CP_WAIT_2() asm volatile("cp.async.wait_group 2;\n" ::: "memory")

__device__ __forceinline__ void ldm4(unsigned* r, const void* p) {
    unsigned a = (unsigned)__cvta_generic_to_shared(p);
    asm volatile("ldmatrix.sync.aligned.m8n8.x4.shared.b16 {%0,%1,%2,%3}, [%4];\n"
        : "=r"(r[0]), "=r"(r[1]), "=r"(r[2]), "=r"(r[3]) : "r"(a));
}
__device__ __forceinline__ void ldm2t(unsigned* r, const void* p) {
    unsigned a = (unsigned)__cvta_generic_to_shared(p);
    asm volatile("ldmatrix.sync.aligned.m8n8.x2.trans.shared.b16 {%0,%1}, [%2];\n"
        : "=r"(r[0]), "=r"(r[1]) : "r"(a));
}
__device__ __forceinline__ void mma16816(float* d, const unsigned* a, const unsigned* b) {
    asm volatile("mma.sync.aligned.m16n8k16.row.col.f32.f16.f16.f32 "
        "{%0,%1,%2,%3}, {%4,%5,%6,%7}, {%8,%9}, {%0,%1,%2,%3};\n"
        : "+f"(d[0]), "+f"(d[1]), "+f"(d[2]), "+f"(d[3])
        : "r"(a[0]), "r"(a[1]), "r"(a[2]), "r"(a[3]), "r"(b[0]), "r"(b[1]));
}

// ---------------- prep: fp32 -> fp16 convert ----------------
__global__ void moe_cvt(const float* __restrict__ src, __half* __restrict__ dst, int n4) {
    int i = blockIdx.x * blockDim.x + threadIdx.x;
    if (i >= n4) return;
    float4 v = ((const float4*)src)[i];
    __half2 a, b;
    a.x = __float2half(v.x); a.y = __float2half(v.y);
    b.x = __float2half(v.z); b.y = __float2half(v.w);
    ((__half2*)dst)[i*2]   = a;
    ((__half2*)dst)[i*2+1] = b;
}

// ---------------- init / gate / routing ----------------
__global__ void moe_init() {
    int t = threadIdx.x;
    if (t < E_) { g_counts[t] = 0; g_cursor[t] = 0; }
}

__global__ void moe_gate(const float* __restrict__ x, const float* __restrict__ gw,
                         const float* __restrict__ gb) {
    int b = blockIdx.x;
    int tid = threadIdx.x;
    const float* xr = x + (size_t)b * D_;
    float acc[E_];
    #pragma unroll
    for (int e = 0; e < E_; e++) acc[e] = 0.f;
    for (int d = tid; d < D_; d += 128) {
        float xv = xr[d];
        const float* g = gw + d * E_;
        #pragma unroll
        for (int e = 0; e < E_; e++) acc[e] += xv * g[e];
    }
    __shared__ float s[E_][128];
    #pragma unroll
    for (int e = 0; e < E_; e++) s[e][tid] = acc[e];
    __syncthreads();
    if (tid < E_) {
        float t = 0.f;
        for (int i = 0; i < 128; i++) t += s[tid][i];
        s[tid][0] = t + gb[tid];
    }
    __syncthreads();
    if (tid == 0) {
        float logit[E_], ex[E_];
        float mx = -1e30f;
        #pragma unroll
        for (int e = 0; e < E_; e++) { logit[e] = s[e][0]; mx = fmaxf(mx, logit[e]); }
        float sum = 0.f;
        #pragma unroll
        for (int e = 0; e < E_; e++) { ex[e] = expf(logit[e] - mx); sum += ex[e]; }
        float inv = 1.f / sum;
        float gts[E_];
        #pragma unroll
        for (int e = 0; e < E_; e++) { gts[e] = ex[e] * inv; g_gates[(size_t)b*E_ + e] = gts[e]; }
        int i0 = 0;
        #pragma unroll
        for (int e = 1; e < E_; e++) if (gts[e] > gts[i0]) i0 = e;
        int i1 = (i0 == 0) ? 1 : 0;
        #pragma unroll
        for (int e = 0; e < E_; e++) if (e != i0 && gts[e] > gts[i1]) i1 = e;
        float v0 = gts[i0], v1 = gts[i1];
        float ws = 1.f / (v0 + v1);
        g_top_idx[b*2]   = i0; g_top_w[b*2]   = v0 * ws;
        g_top_idx[b*2+1] = i1; g_top_w[b*2+1] = v1 * ws;
        atomicAdd(&g_counts[i0], 1);
        atomicAdd(&g_counts[i1], 1);
    }
}

__global__ void moe_usage() {
    int e = blockIdx.x, tid = threadIdx.x;
    float a = 0.f;
    for (int b = tid; b < B_; b += 256) a += g_gates[(size_t)b*E_ + e];
    __shared__ float s[256];
    s[tid] = a; __syncthreads();
    for (int st = 128; st > 0; st >>= 1) {
        if (tid < st) s[tid] += s[tid + st];
        __syncthreads();
    }
    if (tid == 0) g_usage[e] = s[0] / (float)B_;
}

__global__ void moe_offsets() {
    if (threadIdx.x == 0) {
        int acc = 0;
        for (int e = 0; e < E_; e++) { g_offset[e] = acc; acc += g_counts[e]; }
    }
}

__global__ void moe_scatter() {
    int b = blockIdx.x * blockDim.x + threadIdx.x;
    if (b >= B_) return;
    #pragma unroll
    for (int j = 0; j < KSEL; j++) {
        int e = g_top_idx[b*2 + j];
        int p = g_offset[e] + atomicAdd(&g_cursor[e], 1);
        g_list[p] = b;
        g_slot[b*2 + j] = p;
    }
}

// ---------------- grouped GEMM (fp16 single-pass, mma.sync, 4-stage) ----------------
// PHASE1: A = gathered x rows (K=D), B = W1[e] (K-major rows), epi bias+ReLU -> h fp16
// PHASE2: A = h rows (contiguous), B = W2[e], epi bias -> out_buf fp32
#define A_STR 40
#define B_STR 136
#define A_ELE (128*A_STR)
#define B_ELE (32*B_STR)
#define NSTG  4
#define STAGE_ELE (A_ELE + B_ELE)
#define SMEM_BYTES (NSTG * STAGE_ELE * 2)

template<bool PHASE1>
__global__ __launch_bounds__(256, 1) void moe_gemm(const float* __restrict__ bias_all) {
    constexpr int Kdim = PHASE1 ? D_ : H_;
    constexpr int N    = PHASE1 ? H_ : O_;
    constexpr int NKT  = Kdim / 32;

    int e = blockIdx.z;
    int cnt = g_counts[e];
    int mbase = blockIdx.y * 128;
    if (mbase >= cnt) return;
    int off = g_offset[e];
    int nbase = blockIdx.x * 128;

    const __half* __restrict__ Bw =
        (PHASE1 ? g_w1_f16 : g_w2_f16) + (size_t)e * Kdim * N;
    const float* __restrict__ bias_e = bias_all + (size_t)e * N;

    extern __shared__ __half smem[];

    __shared__ int s_rows[128];

    int tid = threadIdx.x;
    int lane = tid & 31, warp = tid >> 5;
    int wm = warp & 1, wn = warp >> 1;

    if (PHASE1 && tid < 128) {
        int rg = mbase + tid;
        s_rows[tid] = g_list[off + (rg < cnt ? rg : 0)];
    }
    __syncthreads();

    auto load_stage = [&](int kt, int stg) {
        int k0 = kt * 32;
        __half* sA = smem + stg * STAGE_ELE;
        __half* sB = sA + A_ELE;
        // A: 128 rows x 32 halves (4 x 16B chunks per row) -> 512 chunks, 2/thread
        #pragma unroll
        for (int it = 0; it < 2; it++) {
            int c = tid + it * 256;
            int row = c >> 2, seg = c & 3;
            const __half* src;
            if (PHASE1) {
                src = g_x_f16 + (size_t)s_rows[row] * D_ + k0 + seg * 8;
            } else {
                size_t r = (size_t)off + mbase + row;
                if (r >= NPAIR) r = NPAIR - 1;
                src = g_h_f16 + r * (size_t)H_ + k0 + seg * 8;
            }
            cp16(sA + row * A_STR + seg * 8, src);
        }
        // B: 32 k-rows x 128 halves (8 x 16B chunks per row... 16 chunks of 8 halves)
        #pragma unroll
        for (int it = 0; it < 2; it++) {
            int c = tid + it * 256;
            int row = c >> 4, seg = c & 15;
            const __half* src = Bw + (size_t)(k0 + row) * N + nbase + seg * 8;
            cp16(sB + row * B_STR + seg * 8, src);
        }
    };

    float acc[4][4][4];
    #pragma unroll
    for (int i = 0; i < 4; i++)
        #pragma unroll
        for (int j = 0; j < 4; j++)
            #pragma unroll
            for (int k = 0; k < 4; k++) acc[i][j][k] = 0.f;

    load_stage(0, 0); cp_commit();
    load_stage(1, 1); cp_commit();
    load_stage(2, 2); cp_commit();

    for (int kt = 0; kt < NKT; kt++) {
        int s = kt & (NSTG - 1);
        CP_WAIT_2();
        __syncthreads();
        // issue next load (or empty group to keep wait_group counting sound)
        if (kt + 3 < NKT) load_stage(kt + 3, (kt + 3) & (NSTG - 1));
        cp_commit();

        const __half* Ahs = smem + s * STAGE_ELE;
        const __half* Bhs = Ahs + A_ELE;

        #pragma unroll
        for (int ks = 0; ks < 32; ks += 16) {
            unsigned ah[4][4];
            int ar = wm * 64 + (lane & 15);
            int acw = ks + ((lane >> 4) << 3);
            #pragma unroll
            for (int mi = 0; mi < 4; mi++)
                ldm4(ah[mi], Ahs + (ar + mi * 16) * A_STR + acw);
            unsigned bh[4][2];
            int kk = ks + (lane & 15);
            #pragma unroll
            for (int nj = 0; nj < 4; nj++)
                ldm2t(bh[nj], Bhs + kk * B_STR + wn * 32 + nj * 8);
            #pragma unroll
            for (int mi = 0; mi < 4; mi++)
                #pragma unroll
                for (int nj = 0; nj < 4; nj++)
                    mma16816(acc[mi][nj], ah[mi], bh[nj]);
        }
    }

    // epilogue
    #pragma unroll
    for (int mi = 0; mi < 4; mi++) {
        #pragma unroll
        for (int nj = 0; nj < 4; nj++) {
            int rloc = wm * 64 + mi * 16 + (lane >> 2);
            int col0 = nbase + wn * 32 + nj * 8 + (lane & 3) * 2;
            float bv0 = bias_e[col0], bv1 = bias_e[col0 + 1];
            #pragma unroll
            for (int half = 0; half < 2; half++) {
                int rg = mbase + rloc + half * 8;
                if (rg < cnt) {
                    float v0 = acc[mi][nj][half*2]     + bv0;
                    float v1 = acc[mi][nj][half*2 + 1] + bv1;
                    size_t rp = (size_t)(off + rg);
                    if (PHASE1) {
                        v0 = fmaxf(v0, 0.f); v1 = fmaxf(v1, 0.f);
                        __half2 hh;
                        hh.x = __float2half(v0); hh.y = __float2half(v1);
                        *(__half2*)(g_h_f16 + rp * H_ + col0) = hh;
                    } else {
                        float2 f; f.x = v0; f.y = v1;
                        *(float2*)(g_out_buf + rp * O_ + col0) = f;
                    }
                }
            }
        }
    }
}

// ---------------- epilogues ----------------
__global__ void moe_combine(float* __restrict__ out) {
    int b = blockIdx.x, t = threadIdx.x;
    int s0 = g_slot[b*2], s1 = g_slot[b*2 + 1];
    float w0 = g_top_w[b*2], w1 = g_top_w[b*2 + 1];
    float4 a = ((const float4*)(g_out_buf + (size_t)s0 * O_))[t];
    float4 c = ((const float4*)(g_out_buf + (size_t)s1 * O_))[t];
    float4 r;
    r.x = w0*a.x + w1*c.x; r.y = w0*a.y + w1*c.y;
    r.z = w0*a.z + w1*c.z; r.w = w0*a.w + w1*c.w;
    ((float4*)(out + (size_t)b * O_))[t] = r;
}

__global__ void moe_avg_part() {
    int e = blockIdx.x, cb = blockIdx.y, ch = blockIdx.z;
    int col = cb * 128 + threadIdx.x;
    int cnt = g_counts[e], off = g_offset[e];
    int per = (cnt + AVG_CH - 1) / AVG_CH;
    int r0 = ch * per;
    int r1 = min(r0 + per, cnt);
    float a = 0.f;
    for (int r = r0; r < r1; r++) a += g_out_buf[(size_t)(off + r) * O_ + col];
    g_avg_part[((size_t)(e * AVG_CH) + ch) * O_ + col] = a;
}

__global__ void moe_avg_fin() {
    int e = blockIdx.x;
    int col = blockIdx.y * 128 + threadIdx.x;
    float a = 0.f;
    #pragma unroll
    for (int c = 0; c < AVG_CH; c++) a += g_avg_part[((size_t)(e * AVG_CH) + c) * O_ + col];
    int cnt = g_counts[e];
    g_avgs[(size_t)e * O_ + col] = a / fmaxf((float)cnt, 1.0f);
}

__global__ void moe_loss(float* __restrict__ out) {
    int tid = threadIdx.x;
    __shared__ float red[256];
    __shared__ float total;
    if (tid == 0) total = 0.f;
    __syncthreads();
    for (int i = 0; i < E_; i++) {
        for (int j = i + 1; j < E_; j++) {
            float s = 0.f;
            bool ok = (g_counts[i] > 0) && (g_counts[j] > 0);
            if (ok) {
                for (int c = tid; c < O_; c += 256) {
                    float d = g_avgs[(size_t)i*O_ + c] - g_avgs[(size_t)j*O_ + c];
                    s += d * d;
                }
            }
            red[tid] = s; __syncthreads();
            for (int st = 128; st > 0; st >>= 1) {
                if (tid < st) red[tid] += red[tid + st];
                __syncthreads();
            }
            if (tid == 0 && ok) total += expf(-red[0] * 0.5f);
            __syncthreads();
        }
    }
    if (tid == 0) {
        out[(size_t)B_ * O_] = total;
        float s = 0.f;
        #pragma unroll
        for (int e = 0; e < E_; e++) {
            float d = g_usage[e] - 1.0f / (float)E_;
            s += d * d;
        }
        out[(size_t)B_ * O_ + 1] = sqrtf(s);
    }
}

// ---------------- launcher ----------------
extern "C" void kernel_launch(void* const* d_in, const int* in_sizes, int n_in,
                              void* d_out, int out_size) {
    const float* x   = (const float*)d_in[0];
    const float* gW  = (const float*)d_in[1];
    const float* gb  = (const float*)d_in[2];
    const float* W1  = (const float*)d_in[3];
    const float* b1  = (const float*)d_in[4];
    const float* W2  = (const float*)d_in[5];
    const float* b2  = (const float*)d_in[6];
    float* out = (float*)d_out;

    cudaFuncSetAttribute(moe_gemm<true>,  cudaFuncAttributeMaxDynamicSharedMemorySize, SMEM_BYTES);
    cudaFuncSetAttribute(moe_gemm<false>, cudaFuncAttributeMaxDynamicSharedMemorySize, SMEM_BYTES);

    __half *xf, *w1f, *w2f;
    cudaGetSymbolAddress((void**)&xf,  g_x_f16);
    cudaGetSymbolAddress((void**)&w1f, g_w1_f16);
    cudaGetSymbolAddress((void**)&w2f, g_w2_f16);

    moe_init<<<1, 32>>>();

    {
        int n4 = (B_ * D_) / 4;
        moe_cvt<<<(n4 + 255) / 256, 256>>>(x, xf, n4);
    }
    {
        int n4 = (E_ * D_ * H_) / 4;
        moe_cvt<<<(n4 + 255) / 256, 256>>>(W1, w1f, n4);
    }
    {
        int n4 = (E_ * H_ * O_) / 4;
        moe_cvt<<<(n4 + 255) / 256, 256>>>(W2, w2f, n4);
    }

    moe_gate<<<B_, 128>>>(x, gW, gb);
    moe_usage<<<E_, 256>>>();
    moe_offsets<<<1, 1>>>();
    moe_scatter<<<(B_ + 255) / 256, 256>>>();

    // per-expert cnt <= B_, so 64 m-tiles suffice
    moe_gemm<true><<<dim3(H_ / 128, 64, E_), 256, SMEM_BYTES>>>(b1);
    moe_gemm<false><<<dim3(O_ / 128, 64, E_), 256, SMEM_BYTES>>>(b2);

    moe_combine<<<B_, 256>>>(out);
    moe_avg_part<<<dim3(E_, O_ / 128, AVG_CH), 128>>>();
    moe_avg_fin<<<dim3(E_, O_ / 128), 128>>>();
    moe_loss<<<1, 256>>>(out);

    (void)in_sizes; (void)n_in; (void)out_size;
}

// round 6
// speedup vs baseline: 2.3376x; 1.1659x over previous
#include <cuda_runtime.h>
#include <cuda_bf16.h>
#include <cuda_fp16.h>
#include <math.h>
#include <stdint.h>

#define B_    8192
#define D_    1024
#define H_    4096
#define O_    1024
#define E_    8
#define KSEL  2
#define NPAIR (B_*KSEL)
#define AVG_CH 16

// ---------------- device scratch (static, no allocation) ----------------
__device__ __half g_x_f16[(size_t)B_*D_];
__device__ __half g_w1_f16[(size_t)E_*D_*H_];   // (E, D, H) K-major rows
__device__ __half g_w2_f16[(size_t)E_*H_*O_];   // (E, H, O)
__device__ __half g_h_f16[(size_t)NPAIR*H_];
__device__ float g_out_buf[(size_t)NPAIR*O_];
__device__ float g_gates[(size_t)B_*E_];
__device__ int   g_top_idx[B_*KSEL];
__device__ float g_top_w[B_*KSEL];
__device__ int   g_counts[E_];
__device__ int   g_cursor[E_];
__device__ int   g_offset[E_];
__device__ int   g_list[NPAIR];
__device__ int   g_slot[B_*KSEL];
__device__ float g_usage[E_];
__device__ float g_avg_part[E_*AVG_CH*O_];
__device__ float g_avgs[E_*O_];

// ---------------- PTX helpers ----------------
__device__ __forceinline__ void cp16(void* s, const void* g) {
    unsigned sa = (unsigned)__cvta_generic_to_shared(s);
    asm volatile("cp.async.ca.shared.global [%0], [%1], 16;\n" :: "r"(sa), "l"(g));
}
__device__ __forceinline__ void cp_commit() { asm volatile("cp.async.commit_group;\n"); }
#define CP_WAIT_2() asm volatile("cp.async.wait_group 2;\n" ::: "memory")

__device__ __forceinline__ void ldm4(unsigned* r, const void* p) {
    unsigned a = (unsigned)__cvta_generic_to_shared(p);
    asm volatile("ldmatrix.sync.aligned.m8n8.x4.shared.b16 {%0,%1,%2,%3}, [%4];\n"
        : "=r"(r[0]), "=r"(r[1]), "=r"(r[2]), "=r"(r[3]) : "r"(a));
}
__device__ __forceinline__ void ldm2t(unsigned* r, const void* p) {
    unsigned a = (unsigned)__cvta_generic_to_shared(p);
    asm volatile("ldmatrix.sync.aligned.m8n8.x2.trans.shared.b16 {%0,%1}, [%2];\n"
        : "=r"(r[0]), "=r"(r[1]) : "r"(a));
}
__device__ __forceinline__ void mma16816(float* d, const unsigned* a, const unsigned* b) {
    asm volatile("mma.sync.aligned.m16n8k16.row.col.f32.f16.f16.f32 "
        "{%0,%1,%2,%3}, {%4,%5,%6,%7}, {%8,%9}, {%0,%1,%2,%3};\n"
        : "+f"(d[0]), "+f"(d[1]), "+f"(d[2]), "+f"(d[3])
        : "r"(a[0]), "r"(a[1]), "r"(a[2]), "r"(a[3]), "r"(b[0]), "r"(b[1]));
}

// ---------------- prep: fp32 -> fp16 convert ----------------
__global__ void moe_cvt(const float* __restrict__ src, __half* __restrict__ dst, int n4) {
    int i = blockIdx.x * blockDim.x + threadIdx.x;
    if (i >= n4) return;
    float4 v = ((const float4*)src)[i];
    __half2 a, b;
    a.x = __float2half(v.x); a.y = __float2half(v.y);
    b.x = __float2half(v.z); b.y = __float2half(v.w);
    ((__half2*)dst)[i*2]   = a;
    ((__half2*)dst)[i*2+1] = b;
}

// ---------------- init / gate / routing ----------------
__global__ void moe_init() {
    int t = threadIdx.x;
    if (t < E_) { g_counts[t] = 0; g_cursor[t] = 0; }
}

__global__ void moe_gate(const float* __restrict__ x, const float* __restrict__ gw,
                         const float* __restrict__ gb) {
    int b = blockIdx.x;
    int tid = threadIdx.x;
    const float* xr = x + (size_t)b * D_;
    float acc[E_];
    #pragma unroll
    for (int e = 0; e < E_; e++) acc[e] = 0.f;
    for (int d = tid; d < D_; d += 128) {
        float xv = xr[d];
        const float* g = gw + d * E_;
        #pragma unroll
        for (int e = 0; e < E_; e++) acc[e] += xv * g[e];
    }
    __shared__ float s[E_][128];
    #pragma unroll
    for (int e = 0; e < E_; e++) s[e][tid] = acc[e];
    __syncthreads();
    if (tid < E_) {
        float t = 0.f;
        for (int i = 0; i < 128; i++) t += s[tid][i];
        s[tid][0] = t + gb[tid];
    }
    __syncthreads();
    if (tid == 0) {
        float logit[E_], ex[E_];
        float mx = -1e30f;
        #pragma unroll
        for (int e = 0; e < E_; e++) { logit[e] = s[e][0]; mx = fmaxf(mx, logit[e]); }
        float sum = 0.f;
        #pragma unroll
        for (int e = 0; e < E_; e++) { ex[e] = expf(logit[e] - mx); sum += ex[e]; }
        float inv = 1.f / sum;
        float gts[E_];
        #pragma unroll
        for (int e = 0; e < E_; e++) { gts[e] = ex[e] * inv; g_gates[(size_t)b*E_ + e] = gts[e]; }
        int i0 = 0;
        #pragma unroll
        for (int e = 1; e < E_; e++) if (gts[e] > gts[i0]) i0 = e;
        int i1 = (i0 == 0) ? 1 : 0;
        #pragma unroll
        for (int e = 0; e < E_; e++) if (e != i0 && gts[e] > gts[i1]) i1 = e;
        float v0 = gts[i0], v1 = gts[i1];
        float ws = 1.f / (v0 + v1);
        g_top_idx[b*2]   = i0; g_top_w[b*2]   = v0 * ws;
        g_top_idx[b*2+1] = i1; g_top_w[b*2+1] = v1 * ws;
        atomicAdd(&g_counts[i0], 1);
        atomicAdd(&g_counts[i1], 1);
    }
}

__global__ void moe_usage() {
    int e = blockIdx.x, tid = threadIdx.x;
    float a = 0.f;
    for (int b = tid; b < B_; b += 256) a += g_gates[(size_t)b*E_ + e];
    __shared__ float s[256];
    s[tid] = a; __syncthreads();
    for (int st = 128; st > 0; st >>= 1) {
        if (tid < st) s[tid] += s[tid + st];
        __syncthreads();
    }
    if (tid == 0) g_usage[e] = s[0] / (float)B_;
}

__global__ void moe_offsets() {
    if (threadIdx.x == 0) {
        int acc = 0;
        for (int e = 0; e < E_; e++) { g_offset[e] = acc; acc += g_counts[e]; }
    }
}

__global__ void moe_scatter() {
    int b = blockIdx.x * blockDim.x + threadIdx.x;
    if (b >= B_) return;
    #pragma unroll
    for (int j = 0; j < KSEL; j++) {
        int e = g_top_idx[b*2 + j];
        int p = g_offset[e] + atomicAdd(&g_cursor[e], 1);
        g_list[p] = b;
        g_slot[b*2 + j] = p;
    }
}

// ---------------- grouped GEMM (fp16, mma.sync, 128x256 tile, 4-stage) ----------------
// PHASE1: A = gathered x rows (K=D), B = W1[e] (K-major rows), epi bias+ReLU -> h fp16
// PHASE2: A = h rows (contiguous), B = W2[e], epi bias -> out_buf fp32
#define TN    256
#define A_STR 40
#define B_STR 264
#define A_ELE (128*A_STR)
#define B_ELE (32*B_STR)
#define NSTG  4
#define STAGE_ELE (A_ELE + B_ELE)
#define SMEM_BYTES (NSTG * STAGE_ELE * 2)

template<bool PHASE1>
__global__ __launch_bounds__(256, 1) void moe_gemm(const float* __restrict__ bias_all) {
    constexpr int Kdim = PHASE1 ? D_ : H_;
    constexpr int N    = PHASE1 ? H_ : O_;
    constexpr int NKT  = Kdim / 32;

    int e = blockIdx.z;
    int cnt = g_counts[e];
    int mbase = blockIdx.y * 128;
    if (mbase >= cnt) return;
    int off = g_offset[e];
    int nbase = blockIdx.x * TN;

    const __half* __restrict__ Bw =
        (PHASE1 ? g_w1_f16 : g_w2_f16) + (size_t)e * Kdim * N;
    const float* __restrict__ bias_e = bias_all + (size_t)e * N;

    extern __shared__ __half smem[];
    __shared__ int s_rows[128];

    int tid = threadIdx.x;
    int lane = tid & 31, warp = tid >> 5;
    int wm = warp & 1, wn = warp >> 1;

    if (PHASE1 && tid < 128) {
        int rg = mbase + tid;
        s_rows[tid] = g_list[off + (rg < cnt ? rg : 0)];
    }
    __syncthreads();

    auto load_stage = [&](int kt, int stg) {
        int k0 = kt * 32;
        __half* sA = smem + stg * STAGE_ELE;
        __half* sB = sA + A_ELE;
        // A: 128 rows x 32 halves -> 512 chunks of 8 halves, 2/thread
        #pragma unroll
        for (int it = 0; it < 2; it++) {
            int c = tid + it * 256;
            int row = c >> 2, seg = c & 3;
            const __half* src;
            if (PHASE1) {
                src = g_x_f16 + (size_t)s_rows[row] * D_ + k0 + seg * 8;
            } else {
                size_t r = (size_t)off + mbase + row;
                if (r >= NPAIR) r = NPAIR - 1;
                src = g_h_f16 + r * (size_t)H_ + k0 + seg * 8;
            }
            cp16(sA + row * A_STR + seg * 8, src);
        }
        // B: 32 k-rows x 256 halves -> 1024 chunks of 8 halves, 4/thread
        #pragma unroll
        for (int it = 0; it < 4; it++) {
            int c = tid + it * 256;
            int row = c >> 5, seg = c & 31;
            const __half* src = Bw + (size_t)(k0 + row) * N + nbase + seg * 8;
            cp16(sB + row * B_STR + seg * 8, src);
        }
    };

    float acc[4][8][4];
    #pragma unroll
    for (int i = 0; i < 4; i++)
        #pragma unroll
        for (int j = 0; j < 8; j++)
            #pragma unroll
            for (int k = 0; k < 4; k++) acc[i][j][k] = 0.f;

    load_stage(0, 0); cp_commit();
    load_stage(1, 1); cp_commit();
    load_stage(2, 2); cp_commit();

    for (int kt = 0; kt < NKT; kt++) {
        int s = kt & (NSTG - 1);
        CP_WAIT_2();
        __syncthreads();
        if (kt + 3 < NKT) load_stage(kt + 3, (kt + 3) & (NSTG - 1));
        cp_commit();

        const __half* Ahs = smem + s * STAGE_ELE;
        const __half* Bhs = Ahs + A_ELE;

        #pragma unroll
        for (int ks = 0; ks < 32; ks += 16) {
            unsigned ah[4][4];
            int ar = wm * 64 + (lane & 15);
            int acw = ks + ((lane >> 4) << 3);
            #pragma unroll
            for (int mi = 0; mi < 4; mi++)
                ldm4(ah[mi], Ahs + (ar + mi * 16) * A_STR + acw);
            unsigned bh[8][2];
            int kk = ks + (lane & 15);
            #pragma unroll
            for (int nj = 0; nj < 8; nj++)
                ldm2t(bh[nj], Bhs + kk * B_STR + wn * 64 + nj * 8);
            #pragma unroll
            for (int mi = 0; mi < 4; mi++)
                #pragma unroll
                for (int nj = 0; nj < 8; nj++)
                    mma16816(acc[mi][nj], ah[mi], bh[nj]);
        }
    }

    // epilogue
    #pragma unroll
    for (int mi = 0; mi < 4; mi++) {
        #pragma unroll
        for (int nj = 0; nj < 8; nj++) {
            int rloc = wm * 64 + mi * 16 + (lane >> 2);
            int col0 = nbase + wn * 64 + nj * 8 + (lane & 3) * 2;
            float bv0 = bias_e[col0], bv1 = bias_e[col0 + 1];
            #pragma unroll
            for (int half = 0; half < 2; half++) {
                int rg = mbase + rloc + half * 8;
                if (rg < cnt) {
                    float v0 = acc[mi][nj][half*2]     + bv0;
                    float v1 = acc[mi][nj][half*2 + 1] + bv1;
                    size_t rp = (size_t)(off + rg);
                    if (PHASE1) {
                        v0 = fmaxf(v0, 0.f); v1 = fmaxf(v1, 0.f);
                        __half2 hh;
                        hh.x = __float2half(v0); hh.y = __float2half(v1);
                        *(__half2*)(g_h_f16 + rp * H_ + col0) = hh;
                    } else {
                        float2 f; f.x = v0; f.y = v1;
                        *(float2*)(g_out_buf + rp * O_ + col0) = f;
                    }
                }
            }
        }
    }
}

// ---------------- epilogues ----------------
__global__ void moe_combine(float* __restrict__ out) {
    int b = blockIdx.x, t = threadIdx.x;
    int s0 = g_slot[b*2], s1 = g_slot[b*2 + 1];
    float w0 = g_top_w[b*2], w1 = g_top_w[b*2 + 1];
    float4 a = ((const float4*)(g_out_buf + (size_t)s0 * O_))[t];
    float4 c = ((const float4*)(g_out_buf + (size_t)s1 * O_))[t];
    float4 r;
    r.x = w0*a.x + w1*c.x; r.y = w0*a.y + w1*c.y;
    r.z = w0*a.z + w1*c.z; r.w = w0*a.w + w1*c.w;
    ((float4*)(out + (size_t)b * O_))[t] = r;
}

__global__ void moe_avg_part() {
    int e = blockIdx.x, cb = blockIdx.y, ch = blockIdx.z;
    int col = cb * 128 + threadIdx.x;
    int cnt = g_counts[e], off = g_offset[e];
    int per = (cnt + AVG_CH - 1) / AVG_CH;
    int r0 = ch * per;
    int r1 = min(r0 + per, cnt);
    float a = 0.f;
    for (int r = r0; r < r1; r++) a += g_out_buf[(size_t)(off + r) * O_ + col];
    g_avg_part[((size_t)(e * AVG_CH) + ch) * O_ + col] = a;
}

__global__ void moe_avg_fin() {
    int e = blockIdx.x;
    int col = blockIdx.y * 128 + threadIdx.x;
    float a = 0.f;
    #pragma unroll
    for (int c = 0; c < AVG_CH; c++) a += g_avg_part[((size_t)(e * AVG_CH) + c) * O_ + col];
    int cnt = g_counts[e];
    g_avgs[(size_t)e * O_ + col] = a / fmaxf((float)cnt, 1.0f);
}

__global__ void moe_loss(float* __restrict__ out) {
    int tid = threadIdx.x;
    __shared__ float red[256];
    __shared__ float total;
    if (tid == 0) total = 0.f;
    __syncthreads();
    for (int i = 0; i < E_; i++) {
        for (int j = i + 1; j < E_; j++) {
            float s = 0.f;
            bool ok = (g_counts[i] > 0) && (g_counts[j] > 0);
            if (ok) {
                for (int c = tid; c < O_; c += 256) {
                    float d = g_avgs[(size_t)i*O_ + c] - g_avgs[(size_t)j*O_ + c];
                    s += d * d;
                }
            }
            red[tid] = s; __syncthreads();
            for (int st = 128; st > 0; st >>= 1) {
                if (tid < st) red[tid] += red[tid + st];
                __syncthreads();
            }
            if (tid == 0 && ok) total += expf(-red[0] * 0.5f);
            __syncthreads();
        }
    }
    if (tid == 0) {
        out[(size_t)B_ * O_] = total;
        float s = 0.f;
        #pragma unroll
        for (int e = 0; e < E_; e++) {
            float d = g_usage[e] - 1.0f / (float)E_;
            s += d * d;
        }
        out[(size_t)B_ * O_ + 1] = sqrtf(s);
    }
}

// ---------------- launcher ----------------
extern "C" void kernel_launch(void* const* d_in, const int* in_sizes, int n_in,
                              void* d_out, int out_size) {
    const float* x   = (const float*)d_in[0];
    const float* gW  = (const float*)d_in[1];
    const float* gb  = (const float*)d_in[2];
    const float* W1  = (const float*)d_in[3];
    const float* b1  = (const float*)d_in[4];
    const float* W2  = (const float*)d_in[5];
    const float* b2  = (const float*)d_in[6];
    float* out = (float*)d_out;

    cudaFuncSetAttribute(moe_gemm<true>,  cudaFuncAttributeMaxDynamicSharedMemorySize, SMEM_BYTES);
    cudaFuncSetAttribute(moe_gemm<false>, cudaFuncAttributeMaxDynamicSharedMemorySize, SMEM_BYTES);

    __half *xf, *w1f, *w2f;
    cudaGetSymbolAddress((void**)&xf,  g_x_f16);
    cudaGetSymbolAddress((void**)&w1f, g_w1_f16);
    cudaGetSymbolAddress((void**)&w2f, g_w2_f16);

    moe_init<<<1, 32>>>();

    {
        int n4 = (B_ * D_) / 4;
        moe_cvt<<<(n4 + 255) / 256, 256>>>(x, xf, n4);
    }
    {
        int n4 = (E_ * D_ * H_) / 4;
        moe_cvt<<<(n4 + 255) / 256, 256>>>(W1, w1f, n4);
    }
    {
        int n4 = (E_ * H_ * O_) / 4;
        moe_cvt<<<(n4 + 255) / 256, 256>>>(W2, w2f, n4);
    }

    moe_gate<<<B_, 128>>>(x, gW, gb);
    moe_usage<<<E_, 256>>>();
    moe_offsets<<<1, 1>>>();
    moe_scatter<<<(B_ + 255) / 256, 256>>>();

    moe_gemm<true><<<dim3(H_ / TN, 64, E_), 256, SMEM_BYTES>>>(b1);
    moe_gemm<false><<<dim3(O_ / TN, 64, E_), 256, SMEM_BYTES>>>(b2);

    moe_combine<<<B_, 256>>>(out);
    moe_avg_part<<<dim3(E_, O_ / 128, AVG_CH), 128>>>();
    moe_avg_fin<<<dim3(E_, O_ / 128), 128>>>();
    moe_loss<<<1, 256>>>(out);

    (void)in_sizes; (void)n_in; (void)out_size;
}

// round 7
// speedup vs baseline: 2.6101x; 1.1166x over previous
#include <cuda_runtime.h>
#include <cuda_bf16.h>
#include <cuda_fp16.h>
#include <math.h>
#include <stdint.h>

#define B_    8192
#define D_    1024
#define H_    4096
#define O_    1024
#define E_    8
#define KSEL  2
#define NPAIR (B_*KSEL)
#define AVG_CH 16

// ---------------- device scratch (static, no allocation) ----------------
__device__ __half g_x_f16[(size_t)B_*D_];
__device__ __half g_w1_f16[(size_t)E_*D_*H_];   // (E, D, H) K-major rows
__device__ __half g_w2_f16[(size_t)E_*H_*O_];   // (E, H, O)
__device__ __half g_h_f16[(size_t)NPAIR*H_];
__device__ float g_out_buf[(size_t)NPAIR*O_];
__device__ float g_gates[(size_t)B_*E_];
__device__ int   g_top_idx[B_*KSEL];
__device__ float g_top_w[B_*KSEL];
__device__ int   g_counts[E_];
__device__ int   g_cursor[E_];
__device__ int   g_offset[E_];
__device__ int   g_list[NPAIR];
__device__ int   g_slot[B_*KSEL];
__device__ float g_usage[E_];
__device__ float g_avg_part[E_*AVG_CH*O_];
__device__ float g_avgs[E_*O_];

// ---------------- PTX helpers ----------------
__device__ __forceinline__ void cp16(void* s, const void* g) {
    unsigned sa = (unsigned)__cvta_generic_to_shared(s);
    asm volatile("cp.async.ca.shared.global [%0], [%1], 16;\n" :: "r"(sa), "l"(g));
}
__device__ __forceinline__ void cp_commit() { asm volatile("cp.async.commit_group;\n"); }
#define CP_WAIT_1() asm volatile("cp.async.wait_group 1;\n" ::: "memory")

__device__ __forceinline__ void ldm4(unsigned* r, const void* p) {
    unsigned a = (unsigned)__cvta_generic_to_shared(p);
    asm volatile("ldmatrix.sync.aligned.m8n8.x4.shared.b16 {%0,%1,%2,%3}, [%4];\n"
        : "=r"(r[0]), "=r"(r[1]), "=r"(r[2]), "=r"(r[3]) : "r"(a));
}
__device__ __forceinline__ void ldm2t(unsigned* r, const void* p) {
    unsigned a = (unsigned)__cvta_generic_to_shared(p);
    asm volatile("ldmatrix.sync.aligned.m8n8.x2.trans.shared.b16 {%0,%1}, [%2];\n"
        : "=r"(r[0]), "=r"(r[1]) : "r"(a));
}
__device__ __forceinline__ void mma16816(float* d, const unsigned* a, const unsigned* b) {
    asm volatile("mma.sync.aligned.m16n8k16.row.col.f32.f16.f16.f32 "
        "{%0,%1,%2,%3}, {%4,%5,%6,%7}, {%8,%9}, {%0,%1,%2,%3};\n"
        : "+f"(d[0]), "+f"(d[1]), "+f"(d[2]), "+f"(d[3])
        : "r"(a[0]), "r"(a[1]), "r"(a[2]), "r"(a[3]), "r"(b[0]), "r"(b[1]));
}

// ---------------- prep: fp32 -> fp16 convert (weights) ----------------
__global__ void moe_cvt(const float* __restrict__ src, __half* __restrict__ dst, int n4) {
    int i = blockIdx.x * blockDim.x + threadIdx.x;
    if (i >= n4) return;
    float4 v = ((const float4*)src)[i];
    __half2 a, b;
    a.x = __float2half(v.x); a.y = __float2half(v.y);
    b.x = __float2half(v.z); b.y = __float2half(v.w);
    ((__half2*)dst)[i*2]   = a;
    ((__half2*)dst)[i*2+1] = b;
}

// ---------------- init / gate / routing ----------------
__global__ void moe_init() {
    int t = threadIdx.x;
    if (t < E_) { g_counts[t] = 0; g_cursor[t] = 0; }
}

// gate + fused x->fp16 conversion
__global__ void moe_gate(const float* __restrict__ x, const float* __restrict__ gw,
                         const float* __restrict__ gb) {
    int b = blockIdx.x;
    int tid = threadIdx.x;
    const float* xr = x + (size_t)b * D_;
    __half* xo = g_x_f16 + (size_t)b * D_;
    float acc[E_];
    #pragma unroll
    for (int e = 0; e < E_; e++) acc[e] = 0.f;
    for (int d = tid; d < D_; d += 128) {
        float xv = xr[d];
        xo[d] = __float2half(xv);
        const float* g = gw + d * E_;
        #pragma unroll
        for (int e = 0; e < E_; e++) acc[e] += xv * g[e];
    }
    __shared__ float s[E_][128];
    #pragma unroll
    for (int e = 0; e < E_; e++) s[e][tid] = acc[e];
    __syncthreads();
    if (tid < E_) {
        float t = 0.f;
        for (int i = 0; i < 128; i++) t += s[tid][i];
        s[tid][0] = t + gb[tid];
    }
    __syncthreads();
    if (tid == 0) {
        float logit[E_], ex[E_];
        float mx = -1e30f;
        #pragma unroll
        for (int e = 0; e < E_; e++) { logit[e] = s[e][0]; mx = fmaxf(mx, logit[e]); }
        float sum = 0.f;
        #pragma unroll
        for (int e = 0; e < E_; e++) { ex[e] = expf(logit[e] - mx); sum += ex[e]; }
        float inv = 1.f / sum;
        float gts[E_];
        #pragma unroll
        for (int e = 0; e < E_; e++) { gts[e] = ex[e] * inv; g_gates[(size_t)b*E_ + e] = gts[e]; }
        int i0 = 0;
        #pragma unroll
        for (int e = 1; e < E_; e++) if (gts[e] > gts[i0]) i0 = e;
        int i1 = (i0 == 0) ? 1 : 0;
        #pragma unroll
        for (int e = 0; e < E_; e++) if (e != i0 && gts[e] > gts[i1]) i1 = e;
        float v0 = gts[i0], v1 = gts[i1];
        float ws = 1.f / (v0 + v1);
        g_top_idx[b*2]   = i0; g_top_w[b*2]   = v0 * ws;
        g_top_idx[b*2+1] = i1; g_top_w[b*2+1] = v1 * ws;
        atomicAdd(&g_counts[i0], 1);
        atomicAdd(&g_counts[i1], 1);
    }
}

__global__ void moe_usage() {
    int e = blockIdx.x, tid = threadIdx.x;
    float a = 0.f;
    for (int b = tid; b < B_; b += 256) a += g_gates[(size_t)b*E_ + e];
    __shared__ float s[256];
    s[tid] = a; __syncthreads();
    for (int st = 128; st > 0; st >>= 1) {
        if (tid < st) s[tid] += s[tid + st];
        __syncthreads();
    }
    if (tid == 0) g_usage[e] = s[0] / (float)B_;
}

__global__ void moe_offsets() {
    if (threadIdx.x == 0) {
        int acc = 0;
        for (int e = 0; e < E_; e++) { g_offset[e] = acc; acc += g_counts[e]; }
    }
}

__global__ void moe_scatter() {
    int b = blockIdx.x * blockDim.x + threadIdx.x;
    if (b >= B_) return;
    #pragma unroll
    for (int j = 0; j < KSEL; j++) {
        int e = g_top_idx[b*2 + j];
        int p = g_offset[e] + atomicAdd(&g_cursor[e], 1);
        g_list[p] = b;
        g_slot[b*2 + j] = p;
    }
}

// ---------------- grouped GEMM (fp16, mma.sync, 128x256 tile, k-slab 64, 3-stage) ----------------
// PHASE1: A = gathered x rows (K=D), B = W1[e] (K-major rows), epi bias+ReLU -> h fp16
// PHASE2: A = h rows (contiguous), B = W2[e], epi bias -> out_buf fp32
#define TN    256
#define TKS   64
#define A_STR 72
#define B_STR 264
#define A_ELE (128*A_STR)
#define B_ELE (TKS*B_STR)
#define NSTG  3
#define STAGE_ELE (A_ELE + B_ELE)
#define SMEM_BYTES (NSTG * STAGE_ELE * 2)

template<bool PHASE1>
__global__ __launch_bounds__(256, 1) void moe_gemm(const float* __restrict__ bias_all) {
    constexpr int Kdim = PHASE1 ? D_ : H_;
    constexpr int N    = PHASE1 ? H_ : O_;
    constexpr int NKT  = Kdim / TKS;

    int e = blockIdx.z;
    int cnt = g_counts[e];
    int mbase = blockIdx.y * 128;
    if (mbase >= cnt) return;
    int off = g_offset[e];
    int nbase = blockIdx.x * TN;

    const __half* __restrict__ Bw =
        (PHASE1 ? g_w1_f16 : g_w2_f16) + (size_t)e * Kdim * N;
    const float* __restrict__ bias_e = bias_all + (size_t)e * N;

    extern __shared__ __half smem[];
    __shared__ int s_rows[128];

    int tid = threadIdx.x;
    int lane = tid & 31, warp = tid >> 5;
    int wm = warp & 1, wn = warp >> 1;

    if (PHASE1 && tid < 128) {
        int rg = mbase + tid;
        s_rows[tid] = g_list[off + (rg < cnt ? rg : 0)];
    }
    __syncthreads();

    auto load_stage = [&](int kt, int stg) {
        int k0 = kt * TKS;
        __half* sA = smem + stg * STAGE_ELE;
        __half* sB = sA + A_ELE;
        // A: 128 rows x 64 halves -> 1024 chunks of 8 halves, 4/thread
        #pragma unroll
        for (int it = 0; it < 4; it++) {
            int c = tid + it * 256;
            int row = c >> 3, seg = c & 7;
            const __half* src;
            if (PHASE1) {
                src = g_x_f16 + (size_t)s_rows[row] * D_ + k0 + seg * 8;
            } else {
                size_t r = (size_t)off + mbase + row;
                if (r >= NPAIR) r = NPAIR - 1;
                src = g_h_f16 + r * (size_t)H_ + k0 + seg * 8;
            }
            cp16(sA + row * A_STR + seg * 8, src);
        }
        // B: 64 k-rows x 256 halves -> 2048 chunks of 8 halves, 8/thread
        #pragma unroll
        for (int it = 0; it < 8; it++) {
            int c = tid + it * 256;
            int row = c >> 5, seg = c & 31;
            const __half* src = Bw + (size_t)(k0 + row) * N + nbase + seg * 8;
            cp16(sB + row * B_STR + seg * 8, src);
        }
    };

    float acc[4][8][4];
    #pragma unroll
    for (int i = 0; i < 4; i++)
        #pragma unroll
        for (int j = 0; j < 8; j++)
            #pragma unroll
            for (int k = 0; k < 4; k++) acc[i][j][k] = 0.f;

    load_stage(0, 0); cp_commit();
    load_stage(1, 1); cp_commit();

    for (int kt = 0; kt < NKT; kt++) {
        int s = kt % NSTG;
        CP_WAIT_1();
        __syncthreads();
        if (kt + 2 < NKT) load_stage(kt + 2, (kt + 2) % NSTG);
        cp_commit();

        const __half* Ahs = smem + s * STAGE_ELE;
        const __half* Bhs = Ahs + A_ELE;

        #pragma unroll
        for (int ks = 0; ks < TKS; ks += 16) {
            unsigned ah[4][4];
            int ar = wm * 64 + (lane & 15);
            int acw = ks + ((lane >> 4) << 3);
            #pragma unroll
            for (int mi = 0; mi < 4; mi++)
                ldm4(ah[mi], Ahs + (ar + mi * 16) * A_STR + acw);
            unsigned bh[8][2];
            int kk = ks + (lane & 15);
            #pragma unroll
            for (int nj = 0; nj < 8; nj++)
                ldm2t(bh[nj], Bhs + kk * B_STR + wn * 64 + nj * 8);
            #pragma unroll
            for (int mi = 0; mi < 4; mi++)
                #pragma unroll
                for (int nj = 0; nj < 8; nj++)
                    mma16816(acc[mi][nj], ah[mi], bh[nj]);
        }
    }

    // epilogue
    #pragma unroll
    for (int mi = 0; mi < 4; mi++) {
        #pragma unroll
        for (int nj = 0; nj < 8; nj++) {
            int rloc = wm * 64 + mi * 16 + (lane >> 2);
            int col0 = nbase + wn * 64 + nj * 8 + (lane & 3) * 2;
            float bv0 = bias_e[col0], bv1 = bias_e[col0 + 1];
            #pragma unroll
            for (int half = 0; half < 2; half++) {
                int rg = mbase + rloc + half * 8;
                if (rg < cnt) {
                    float v0 = acc[mi][nj][half*2]     + bv0;
                    float v1 = acc[mi][nj][half*2 + 1] + bv1;
                    size_t rp = (size_t)(off + rg);
                    if (PHASE1) {
                        v0 = fmaxf(v0, 0.f); v1 = fmaxf(v1, 0.f);
                        __half2 hh;
                        hh.x = __float2half(v0); hh.y = __float2half(v1);
                        *(__half2*)(g_h_f16 + rp * H_ + col0) = hh;
                    } else {
                        float2 f; f.x = v0; f.y = v1;
                        *(float2*)(g_out_buf + rp * O_ + col0) = f;
                    }
                }
            }
        }
    }
}

// ---------------- epilogues ----------------
__global__ void moe_combine(float* __restrict__ out) {
    int b = blockIdx.x, t = threadIdx.x;
    int s0 = g_slot[b*2], s1 = g_slot[b*2 + 1];
    float w0 = g_top_w[b*2], w1 = g_top_w[b*2 + 1];
    float4 a = ((const float4*)(g_out_buf + (size_t)s0 * O_))[t];
    float4 c = ((const float4*)(g_out_buf + (size_t)s1 * O_))[t];
    float4 r;
    r.x = w0*a.x + w1*c.x; r.y = w0*a.y + w1*c.y;
    r.z = w0*a.z + w1*c.z; r.w = w0*a.w + w1*c.w;
    ((float4*)(out + (size_t)b * O_))[t] = r;
}

__global__ void moe_avg_part() {
    int e = blockIdx.x, cb = blockIdx.y, ch = blockIdx.z;
    int col = cb * 128 + threadIdx.x;
    int cnt = g_counts[e], off = g_offset[e];
    int per = (cnt + AVG_CH - 1) / AVG_CH;
    int r0 = ch * per;
    int r1 = min(r0 + per, cnt);
    float a = 0.f;
    for (int r = r0; r < r1; r++) a += g_out_buf[(size_t)(off + r) * O_ + col];
    g_avg_part[((size_t)(e * AVG_CH) + ch) * O_ + col] = a;
}

__global__ void moe_avg_fin() {
    int e = blockIdx.x;
    int col = blockIdx.y * 128 + threadIdx.x;
    float a = 0.f;
    #pragma unroll
    for (int c = 0; c < AVG_CH; c++) a += g_avg_part[((size_t)(e * AVG_CH) + c) * O_ + col];
    int cnt = g_counts[e];
    g_avgs[(size_t)e * O_ + col] = a / fmaxf((float)cnt, 1.0f);
}

__global__ void moe_loss(float* __restrict__ out) {
    int tid = threadIdx.x;
    __shared__ float red[256];
    __shared__ float total;
    if (tid == 0) total = 0.f;
    __syncthreads();
    for (int i = 0; i < E_; i++) {
        for (int j = i + 1; j < E_; j++) {
            float s = 0.f;
            bool ok = (g_counts[i] > 0) && (g_counts[j] > 0);
            if (ok) {
                for (int c = tid; c < O_; c += 256) {
                    float d = g_avgs[(size_t)i*O_ + c] - g_avgs[(size_t)j*O_ + c];
                    s += d * d;
                }
            }
            red[tid] = s; __syncthreads();
            for (int st = 128; st > 0; st >>= 1) {
                if (tid < st) red[tid] += red[tid + st];
                __syncthreads();
            }
            if (tid == 0 && ok) total += expf(-red[0] * 0.5f);
            __syncthreads();
        }
    }
    if (tid == 0) {
        out[(size_t)B_ * O_] = total;
        float s = 0.f;
        #pragma unroll
        for (int e = 0; e < E_; e++) {
            float d = g_usage[e] - 1.0f / (float)E_;
            s += d * d;
        }
        out[(size_t)B_ * O_ + 1] = sqrtf(s);
    }
}

// ---------------- launcher ----------------
extern "C" void kernel_launch(void* const* d_in, const int* in_sizes, int n_in,
                              void* d_out, int out_size) {
    const float* x   = (const float*)d_in[0];
    const float* gW  = (const float*)d_in[1];
    const float* gb  = (const float*)d_in[2];
    const float* W1  = (const float*)d_in[3];
    const float* b1  = (const float*)d_in[4];
    const float* W2  = (const float*)d_in[5];
    const float* b2  = (const float*)d_in[6];
    float* out = (float*)d_out;

    cudaFuncSetAttribute(moe_gemm<true>,  cudaFuncAttributeMaxDynamicSharedMemorySize, SMEM_BYTES);
    cudaFuncSetAttribute(moe_gemm<false>, cudaFuncAttributeMaxDynamicSharedMemorySize, SMEM_BYTES);

    __half *w1f, *w2f;
    cudaGetSymbolAddress((void**)&w1f, g_w1_f16);
    cudaGetSymbolAddress((void**)&w2f, g_w2_f16);

    moe_init<<<1, 32>>>();

    // gate fuses x->fp16 conversion
    moe_gate<<<B_, 128>>>(x, gW, gb);

    {
        int n4 = (E_ * D_ * H_) / 4;
        moe_cvt<<<(n4 + 255) / 256, 256>>>(W1, w1f, n4);
    }
    {
        int n4 = (E_ * H_ * O_) / 4;
        moe_cvt<<<(n4 + 255) / 256, 256>>>(W2, w2f, n4);
    }

    moe_usage<<<E_, 256>>>();
    moe_offsets<<<1, 1>>>();
    moe_scatter<<<(B_ + 255) / 256, 256>>>();

    moe_gemm<true><<<dim3(H_ / TN, 64, E_), 256, SMEM_BYTES>>>(b1);
    moe_gemm<false><<<dim3(O_ / TN, 64, E_), 256, SMEM_BYTES>>>(b2);

    moe_combine<<<B_, 256>>>(out);
    moe_avg_part<<<dim3(E_, O_ / 128, AVG_CH), 128>>>();
    moe_avg_fin<<<dim3(E_, O_ / 128), 128>>>();
    moe_loss<<<1, 256>>>(out);

    (void)in_sizes; (void)n_in; (void)out_size;
}